// round 1
// baseline (speedup 1.0000x reference)
#include <cuda_runtime.h>
#include <math.h>

#define BB 4
#define SS 4096
#define CCH 128
#define HIDN 256
#define NROWS (BB*SS)      /* 16384 */
#define NCHUNK 16
#define ROWS_PER_CHUNK (SS/NCHUNK)  /* 256 */

/* ------------ scratch (device globals: allocation-free rule) ------------- */
__device__ float g_t   [NROWS*CCH];
__device__ float g_xl  [NROWS*CCH];
__device__ float g_q   [NROWS*CCH];
__device__ float g_k   [NROWS*CCH];
__device__ float g_v   [NROWS*CCH];
__device__ float g_kT  [NROWS*CCH];
__device__ float g_y   [NROWS*CCH];
__device__ float g_ao  [NROWS*CCH];
__device__ float g_fin [NROWS*CCH];
__device__ float g_h   [NROWS*HIDN];
__device__ float g_scores[(size_t)BB*SS*SS];   /* 268 MB */
__device__ float g_pm  [NCHUNK*NROWS];
__device__ float g_ps  [NCHUNK*NROWS];
__device__ float g_off [NROWS];

/* ------------------------- fast exp (FFMA-only) -------------------------- */
__device__ __forceinline__ float fexp(float x) {
    x = fmaxf(x, -80.0f);                       /* flush-to-tiny guard */
    float t = x * 1.4426950408889634f;
    float k = rintf(t);
    float f = fmaf(k, -0.693359375f, x);        /* ln2 hi */
    f = fmaf(k, 2.12194440e-4f, f);             /* ln2 lo */
    float p = fmaf(f, 8.3333333e-3f, 4.1666667e-2f);
    p = fmaf(p, f, 1.6666667e-1f);
    p = fmaf(p, f, 5.0e-1f);
    p = fmaf(p, f, 1.0f);
    p = fmaf(p, f, 1.0f);
    int ki = (int)k;
    float sc = __int_as_float((ki + 127) << 23);
    return p * sc;
}

__device__ __forceinline__ float gelu_exact(float v) {
    return 0.5f * v * (1.0f + erff(v * 0.70710678118654752f));
}

/* --------------------- generic 2D transpose per batch -------------------- */
/* src[z][R][Cc] -> dst[z][Cc][R]; R, Cc multiples of 32 */
__global__ __launch_bounds__(1024) void transpose_k(
    const float* __restrict__ src, float* __restrict__ dst, int R, int Cc)
{
    __shared__ float tile[32][33];
    size_t zo = (size_t)blockIdx.z * R * Cc;
    int c0 = blockIdx.x * 32, r0 = blockIdx.y * 32;
    int x = threadIdx.x, y = threadIdx.y;
    tile[y][x] = src[zo + (size_t)(r0 + y) * Cc + c0 + x];
    __syncthreads();
    dst[zo + (size_t)(c0 + y) * R + r0 + x] = tile[x][y];
}

/* ----------------------------- LayerNorm --------------------------------- */
/* rows of length 128, one warp per row */
__global__ __launch_bounds__(256) void ln_k(
    const float* __restrict__ in, const float* __restrict__ w,
    const float* __restrict__ b, float* __restrict__ out)
{
    int row  = blockIdx.x * 8 + (threadIdx.x >> 5);
    int lane = threadIdx.x & 31;
    size_t base = (size_t)row * CCH + lane * 4;
    float4 v = *(const float4*)&in[base];
    float s = v.x + v.y + v.z + v.w;
    #pragma unroll
    for (int o = 16; o > 0; o >>= 1) s += __shfl_xor_sync(0xffffffffu, s, o);
    float mu = s * (1.0f / 128.0f);
    float dx = v.x - mu, dy = v.y - mu, dz = v.z - mu, dw = v.w - mu;
    float q = dx*dx + dy*dy + dz*dz + dw*dw;
    #pragma unroll
    for (int o = 16; o > 0; o >>= 1) q += __shfl_xor_sync(0xffffffffu, q, o);
    float rstd = rsqrtf(q * (1.0f / 128.0f) + 1e-5f);
    float4 wv = *(const float4*)&w[lane * 4];
    float4 bv = *(const float4*)&b[lane * 4];
    float4 o4;
    o4.x = dx * rstd * wv.x + bv.x;
    o4.y = dy * rstd * wv.y + bv.y;
    o4.z = dz * rstd * wv.z + bv.z;
    o4.w = dw * rstd * wv.w + bv.w;
    *(float4*)&out[base] = o4;
}

/* ------------------------------ GEMM ------------------------------------- */
/* C[m,n] = epi( alpha * sum_k f(A[m,k]) * W[k,n] + bias[n], res[m,n] )
 * A row-major [M,K], W row-major [K,N]. BM=BN=128, BK=8, 256 threads, 8x8/thr.
 * AMODE: 0 = identity, 1 = fexp(a - off[k])  (softmax-normalized scores)
 * EPI:   0 = none, 1 = gelu, 2 = +res, 3 = gelu(v)+res
 * M,N multiples of 128; K multiple of 8. blockIdx.z = batch (strides sA,sW,sC).
 */
template<int AMODE, int EPI>
__global__ __launch_bounds__(256) void gemm_k(
    const float* __restrict__ A, const float* __restrict__ W,
    const float* __restrict__ bias, const float* __restrict__ res,
    float* __restrict__ Cout,
    int M, int N, int K,
    long long sA, long long sW, long long sC,
    const float* __restrict__ off, int sOff,
    float alpha)
{
    __shared__ float As[8][132];
    __shared__ float Bs[8][132];
    int z = blockIdx.z;
    A    += (size_t)z * sA;
    W    += (size_t)z * sW;
    Cout += (size_t)z * sC;

    int m0 = blockIdx.y * 128;
    int n0 = blockIdx.x * 128;
    int t  = threadIdx.x;
    int a_r = t >> 1,  a_c = (t & 1) * 4;
    int b_r = t >> 5,  b_c = (t & 31) * 4;
    int tx  = t & 15,  ty  = t >> 4;

    float acc[8][8];
    #pragma unroll
    for (int i = 0; i < 8; i++)
        #pragma unroll
        for (int j = 0; j < 8; j++) acc[i][j] = 0.0f;

    const float* offp = (AMODE == 1) ? (off + (size_t)z * sOff) : nullptr;

    for (int k0 = 0; k0 < K; k0 += 8) {
        float4 av = *(const float4*)&A[(size_t)(m0 + a_r) * K + k0 + a_c];
        float4 bv = *(const float4*)&W[(size_t)(k0 + b_r) * N + n0 + b_c];
        if (AMODE == 1) {
            av.x = fexp(av.x - __ldg(&offp[k0 + a_c + 0]));
            av.y = fexp(av.y - __ldg(&offp[k0 + a_c + 1]));
            av.z = fexp(av.z - __ldg(&offp[k0 + a_c + 2]));
            av.w = fexp(av.w - __ldg(&offp[k0 + a_c + 3]));
        }
        As[a_c + 0][a_r] = av.x;
        As[a_c + 1][a_r] = av.y;
        As[a_c + 2][a_r] = av.z;
        As[a_c + 3][a_r] = av.w;
        *(float4*)&Bs[b_r][b_c] = bv;
        __syncthreads();

        #pragma unroll
        for (int kk = 0; kk < 8; kk++) {
            float ar[8], br[8];
            *(float4*)&ar[0] = *(const float4*)&As[kk][ty * 8];
            *(float4*)&ar[4] = *(const float4*)&As[kk][ty * 8 + 4];
            *(float4*)&br[0] = *(const float4*)&Bs[kk][tx * 8];
            *(float4*)&br[4] = *(const float4*)&Bs[kk][tx * 8 + 4];
            #pragma unroll
            for (int i = 0; i < 8; i++)
                #pragma unroll
                for (int j = 0; j < 8; j++)
                    acc[i][j] = fmaf(ar[i], br[j], acc[i][j]);
        }
        __syncthreads();
    }

    int crow = m0 + ty * 8;
    int ccol = n0 + tx * 8;
    float bi[8];
    #pragma unroll
    for (int j = 0; j < 8; j++) bi[j] = bias ? bias[ccol + j] : 0.0f;

    #pragma unroll
    for (int i = 0; i < 8; i++) {
        size_t base = (size_t)(crow + i) * N + ccol;
        float v[8];
        #pragma unroll
        for (int j = 0; j < 8; j++) {
            float u = acc[i][j] * alpha + bi[j];
            if (EPI == 1 || EPI == 3) u = gelu_exact(u);
            if (EPI == 2 || EPI == 3) u += res[(size_t)z * sC + base + j];
            v[j] = u;
        }
        *(float4*)&Cout[base + 0] = make_float4(v[0], v[1], v[2], v[3]);
        *(float4*)&Cout[base + 4] = make_float4(v[4], v[5], v[6], v[7]);
    }
}

/* ------------- column (query-axis) softmax stats: partial pass ----------- */
/* grid (SS/128, NCHUNK, BB), block 128. Online max/sumexp over a row chunk. */
__global__ __launch_bounds__(128) void colstat_k(
    const float* __restrict__ s, float* __restrict__ pm, float* __restrict__ ps)
{
    int j  = blockIdx.x * 128 + threadIdx.x;
    int z  = blockIdx.z;
    int i0 = blockIdx.y * ROWS_PER_CHUNK;
    const float* p = s + (size_t)z * SS * SS + (size_t)i0 * SS + j;
    float m = -1e30f, l = 0.0f;
    #pragma unroll 4
    for (int i = 0; i < ROWS_PER_CHUNK; i++) {
        float v = p[(size_t)i * SS];
        if (v <= m) {
            l += fexp(v - m);
        } else {
            l = l * fexp(m - v) + 1.0f;
            m = v;
        }
    }
    size_t o = ((size_t)blockIdx.y * BB + z) * SS + j;
    pm[o] = m;
    ps[o] = l;
}

/* reduce partials -> off[j] = m + log(l) */
__global__ __launch_bounds__(256) void colreduce_k(
    const float* __restrict__ pm, const float* __restrict__ ps,
    float* __restrict__ off)
{
    int idx = blockIdx.x * 256 + threadIdx.x;   /* over BB*SS */
    float m = -1e30f;
    #pragma unroll
    for (int c = 0; c < NCHUNK; c++) m = fmaxf(m, pm[(size_t)c * NROWS + idx]);
    float l = 0.0f;
    #pragma unroll
    for (int c = 0; c < NCHUNK; c++)
        l += ps[(size_t)c * NROWS + idx] * fexp(pm[(size_t)c * NROWS + idx] - m);
    off[idx] = m + logf(l);
}

/* ------------------------------- launch ---------------------------------- */
static float* sym(const void* s) {
    void* p = nullptr;
    cudaGetSymbolAddress(&p, s);
    return (float*)p;
}

extern "C" void kernel_launch(void* const* d_in, const int* in_sizes, int n_in,
                              void* d_out, int out_size)
{
    const float* x    = (const float*)d_in[0];
    const float* ln1w = (const float*)d_in[1];
    const float* ln1b = (const float*)d_in[2];
    const float* wq   = (const float*)d_in[3];
    const float* bq   = (const float*)d_in[4];
    const float* wk   = (const float*)d_in[5];
    const float* bk   = (const float*)d_in[6];
    const float* wv   = (const float*)d_in[7];
    const float* bv   = (const float*)d_in[8];
    const float* wo   = (const float*)d_in[9];
    const float* bo   = (const float*)d_in[10];
    const float* ln2w = (const float*)d_in[11];
    const float* ln2b = (const float*)d_in[12];
    const float* w1   = (const float*)d_in[13];
    const float* b1   = (const float*)d_in[14];
    const float* w2   = (const float*)d_in[15];
    const float* b2   = (const float*)d_in[16];
    float* out = (float*)d_out;

    float* pt   = sym(g_t);
    float* pxl  = sym(g_xl);
    float* pq   = sym(g_q);
    float* pk   = sym(g_k);
    float* pv   = sym(g_v);
    float* pkT  = sym(g_kT);
    float* py   = sym(g_y);
    float* pao  = sym(g_ao);
    float* pfin = sym(g_fin);
    float* ph   = sym(g_h);
    float* psc  = sym(g_scores);
    float* ppm  = sym(g_pm);
    float* pps  = sym(g_ps);
    float* poff = sym(g_off);

    dim3 tb(32, 32);
    const long long sSC = (long long)SS * CCH;   /* 524288 */
    const long long sCS = (long long)CCH * SS;
    const long long sS2 = (long long)SS * SS;    /* 16777216 */

    /* x [B,C,S] -> t [B,S,C] */
    transpose_k<<<dim3(SS/32, CCH/32, BB), tb>>>(x, pt, CCH, SS);

    /* LN1 */
    ln_k<<<NROWS/8, 256>>>(pt, ln1w, ln1b, pxl);

    /* QKV projections: [16384,128] @ [128,128] + b */
    gemm_k<0,0><<<dim3(1, NROWS/128, 1), 256>>>(pxl, wq, bq, nullptr, pq,
        NROWS, CCH, CCH, 0, 0, 0, nullptr, 0, 1.0f);
    gemm_k<0,0><<<dim3(1, NROWS/128, 1), 256>>>(pxl, wk, bk, nullptr, pk,
        NROWS, CCH, CCH, 0, 0, 0, nullptr, 0, 1.0f);
    gemm_k<0,0><<<dim3(1, NROWS/128, 1), 256>>>(pxl, wv, bv, nullptr, pv,
        NROWS, CCH, CCH, 0, 0, 0, nullptr, 0, 1.0f);

    /* k [B,S,C] -> kT [B,C,S] */
    transpose_k<<<dim3(CCH/32, SS/32, BB), tb>>>(pk, pkT, SS, CCH);

    /* scores = 0.25 * q @ kT  (batched) */
    gemm_k<0,0><<<dim3(SS/128, SS/128, BB), 256>>>(pq, pkT, nullptr, nullptr, psc,
        SS, SS, CCH, sSC, sCS, sS2, nullptr, 0, 0.25f);

    /* per-key (column) softmax stats */
    colstat_k<<<dim3(SS/128, NCHUNK, BB), 128>>>(psc, ppm, pps);
    colreduce_k<<<NROWS/256, 256>>>(ppm, pps, poff);

    /* ao = softmax_q(scores) @ v  (exp-normalize applied on A-tile load) */
    gemm_k<1,0><<<dim3(1, SS/128, BB), 256>>>(psc, pv, nullptr, nullptr, pao,
        SS, CCH, SS, sS2, sSC, sSC, poff, SS, 1.0f);

    /* y = ao @ wo + bo + t */
    gemm_k<0,2><<<dim3(1, NROWS/128, 1), 256>>>(pao, wo, bo, pt, py,
        NROWS, CCH, CCH, 0, 0, 0, nullptr, 0, 1.0f);

    /* LN2 */
    ln_k<<<NROWS/8, 256>>>(py, ln2w, ln2b, pxl);

    /* h = gelu(ln2 @ w1 + b1) */
    gemm_k<0,1><<<dim3(HIDN/128, NROWS/128, 1), 256>>>(pxl, w1, b1, nullptr, ph,
        NROWS, HIDN, CCH, 0, 0, 0, nullptr, 0, 1.0f);

    /* fin = gelu(h @ w2 + b2) + y */
    gemm_k<0,3><<<dim3(1, NROWS/128, 1), 256>>>(ph, w2, b2, py, pfin,
        NROWS, CCH, HIDN, 0, 0, 0, nullptr, 0, 1.0f);

    /* fin [B,S,C] -> out [B,C,H,W] */
    transpose_k<<<dim3(CCH/32, SS/32, BB), tb>>>(pfin, out, SS, CCH);
}

// round 4
// speedup vs baseline: 1.8495x; 1.8495x over previous
#include <cuda_runtime.h>
#include <math.h>
#include <stdint.h>

#define BB 4
#define SS 4096
#define CCH 128
#define HIDN 256
#define NROWS (BB*SS)      /* 16384 */
#define NCHUNK 16
#define ROWS_PER_CHUNK (SS/NCHUNK)  /* 256 */

/* ------------ scratch (device globals: allocation-free rule) ------------- */
__device__ float g_t   [NROWS*CCH];
__device__ float g_xl  [NROWS*CCH];
__device__ float g_q   [NROWS*CCH];
__device__ float g_k   [NROWS*CCH];
__device__ float g_v   [NROWS*CCH];
__device__ float g_vT  [NROWS*CCH];
__device__ float g_y   [NROWS*CCH];
__device__ float g_ao  [NROWS*CCH];
__device__ float g_fin [NROWS*CCH];
__device__ float g_h   [NROWS*HIDN];
__device__ float g_scores[(size_t)BB*SS*SS];   /* 268 MB */
__device__ float g_pm  [NCHUNK*NROWS];
__device__ float g_ps  [NCHUNK*NROWS];
__device__ float g_off [NROWS];
__device__ float g_wqT [CCH*CCH];
__device__ float g_wkT [CCH*CCH];
__device__ float g_wvT [CCH*CCH];
__device__ float g_woT [CCH*CCH];
__device__ float g_w1T [CCH*HIDN];
__device__ float g_w2T [CCH*HIDN];

/* ------------------------- fast exp (FFMA-only) -------------------------- */
__device__ __forceinline__ float fexp(float x) {
    x = fmaxf(x, -80.0f);
    float t = x * 1.4426950408889634f;
    float k = rintf(t);
    float f = fmaf(k, -0.693359375f, x);
    f = fmaf(k, 2.12194440e-4f, f);
    float p = fmaf(f, 8.3333333e-3f, 4.1666667e-2f);
    p = fmaf(p, f, 1.6666667e-1f);
    p = fmaf(p, f, 5.0e-1f);
    p = fmaf(p, f, 1.0f);
    p = fmaf(p, f, 1.0f);
    int ki = (int)k;
    float sc = __int_as_float((ki + 127) << 23);
    return p * sc;
}

__device__ __forceinline__ float gelu_exact(float v) {
    return 0.5f * v * (1.0f + erff(v * 0.70710678118654752f));
}

__device__ __forceinline__ float tf32r(float x) {
    uint32_t u;
    asm("cvt.rna.tf32.f32 %0, %1;" : "=r"(u) : "f"(x));
    return __uint_as_float(u);
}

__device__ __forceinline__ void mma_tf32_16n8k8(
    float* d, uint32_t a0, uint32_t a1, uint32_t a2, uint32_t a3,
    uint32_t b0, uint32_t b1)
{
    asm volatile(
        "mma.sync.aligned.m16n8k8.row.col.f32.tf32.tf32.f32 "
        "{%0,%1,%2,%3}, {%4,%5,%6,%7}, {%8,%9}, {%0,%1,%2,%3};"
        : "+f"(d[0]), "+f"(d[1]), "+f"(d[2]), "+f"(d[3])
        : "r"(a0), "r"(a1), "r"(a2), "r"(a3), "r"(b0), "r"(b1));
}

/* --------------------- generic 2D transpose per batch -------------------- */
__global__ __launch_bounds__(1024) void transpose_k(
    const float* __restrict__ src, float* __restrict__ dst, int R, int Cc)
{
    __shared__ float tile[32][33];
    size_t zo = (size_t)blockIdx.z * R * Cc;
    int c0 = blockIdx.x * 32, r0 = blockIdx.y * 32;
    int x = threadIdx.x, y = threadIdx.y;
    tile[y][x] = src[zo + (size_t)(r0 + y) * Cc + c0 + x];
    __syncthreads();
    dst[zo + (size_t)(c0 + y) * R + r0 + x] = tile[x][y];
}

/* ----------------------------- LayerNorm --------------------------------- */
__global__ __launch_bounds__(256) void ln_k(
    const float* __restrict__ in, const float* __restrict__ w,
    const float* __restrict__ b, float* __restrict__ out)
{
    int row  = blockIdx.x * 8 + (threadIdx.x >> 5);
    int lane = threadIdx.x & 31;
    size_t base = (size_t)row * CCH + lane * 4;
    float4 v = *(const float4*)&in[base];
    float s = v.x + v.y + v.z + v.w;
    #pragma unroll
    for (int o = 16; o > 0; o >>= 1) s += __shfl_xor_sync(0xffffffffu, s, o);
    float mu = s * (1.0f / 128.0f);
    float dx = v.x - mu, dy = v.y - mu, dz = v.z - mu, dw = v.w - mu;
    float q = dx*dx + dy*dy + dz*dz + dw*dw;
    #pragma unroll
    for (int o = 16; o > 0; o >>= 1) q += __shfl_xor_sync(0xffffffffu, q, o);
    float rstd = rsqrtf(q * (1.0f / 128.0f) + 1e-5f);
    float4 wv = *(const float4*)&w[lane * 4];
    float4 bv = *(const float4*)&b[lane * 4];
    float4 o4;
    o4.x = dx * rstd * wv.x + bv.x;
    o4.y = dy * rstd * wv.y + bv.y;
    o4.z = dz * rstd * wv.z + bv.z;
    o4.w = dw * rstd * wv.w + bv.w;
    *(float4*)&out[base] = o4;
}

/* ------------------ tf32 mma.sync GEMM: D = A @ B^T ----------------------- */
/* A row-major [M,K], B row-major [N,K] (i.e. B^T col-major). Tile 128x128,
 * BK=32, double-buffered SMEM stride 36 (conflict-free frag loads).
 * 256 threads = 8 warps in 4(M) x 2(N); warp tile 32x64; m16n8k8 tf32.
 * AMODE: 0 identity, 1 fexp(a - off[k]).
 * EPI: 0 alpha only, 1 +bias, 2 +bias+res, 3 gelu(+bias), 4 gelu(+bias)+res.
 */
#define LDA 36
#define ABUF (128*LDA)            /* floats per buffer */
#define GEMM_SMEM (4*ABUF*4)      /* 2 A bufs + 2 B bufs, bytes = 73728 */

template<int AMODE, int EPI>
__global__ __launch_bounds__(256, 1) void gemm_mma(
    const float* __restrict__ A, const float* __restrict__ Bm,
    const float* __restrict__ bias, const float* __restrict__ res,
    float* __restrict__ Cout,
    int N, int K,
    long long sA, long long sB, long long sC,
    const float* __restrict__ off, int sOff, float alpha)
{
    extern __shared__ float sm[];
    float* As[2] = { sm,            sm + ABUF };
    float* Bs[2] = { sm + 2*ABUF,   sm + 3*ABUF };

    int t = threadIdx.x;
    int wid = t >> 5, lane = t & 31;
    int wm = wid & 3, wn = wid >> 2;
    int z = blockIdx.z;
    const float* Ab = A + (size_t)z * sA;
    const float* Bb = Bm + (size_t)z * sB;
    float* Cb = Cout + (size_t)z * sC;
    const float* Rb = (EPI == 2 || EPI == 4) ? res + (size_t)z * sC : nullptr;
    const float* offb = (AMODE == 1) ? off + (size_t)z * sOff : nullptr;
    int m0 = blockIdx.y * 128;
    int n0 = blockIdx.x * 128;

    float acc[2][8][4];
    #pragma unroll
    for (int mt = 0; mt < 2; mt++)
        #pragma unroll
        for (int nt = 0; nt < 8; nt++)
            #pragma unroll
            for (int e = 0; e < 4; e++) acc[mt][nt][e] = 0.0f;

    int nch = K >> 5;

    /* ldg one chunk to regs (with exp + tf32 applied) */
    float4 ra[4], rb[4];
    auto ldg_chunk = [&](int c) {
        int k0 = c << 5;
        #pragma unroll
        for (int i = 0; i < 4; i++) {
            int idx = i * 256 + t;
            int r = idx >> 3, c4 = idx & 7;
            float4 v = *(const float4*)&Ab[(size_t)(m0 + r) * K + k0 + c4 * 4];
            if (AMODE == 1) {
                int kk = k0 + c4 * 4;
                v.x = fexp(v.x - __ldg(offb + kk + 0));
                v.y = fexp(v.y - __ldg(offb + kk + 1));
                v.z = fexp(v.z - __ldg(offb + kk + 2));
                v.w = fexp(v.w - __ldg(offb + kk + 3));
            }
            v.x = tf32r(v.x); v.y = tf32r(v.y); v.z = tf32r(v.z); v.w = tf32r(v.w);
            ra[i] = v;
            float4 w4 = *(const float4*)&Bb[(size_t)(n0 + r) * K + k0 + c4 * 4];
            w4.x = tf32r(w4.x); w4.y = tf32r(w4.y); w4.z = tf32r(w4.z); w4.w = tf32r(w4.w);
            rb[i] = w4;
        }
    };
    auto st_chunk = [&](int buf) {
        #pragma unroll
        for (int i = 0; i < 4; i++) {
            int idx = i * 256 + t;
            int r = idx >> 3, c4 = idx & 7;
            *(float4*)&As[buf][r * LDA + c4 * 4] = ra[i];
            *(float4*)&Bs[buf][r * LDA + c4 * 4] = rb[i];
        }
    };

    ldg_chunk(0);
    st_chunk(0);
    __syncthreads();

    int aR = wm * 32 + (lane >> 2);
    int bR = wn * 64 + (lane >> 2);
    int kc0 = lane & 3;

    for (int c = 0; c < nch; c++) {
        if (c + 1 < nch) ldg_chunk(c + 1);
        const float* Ap = As[c & 1];
        const float* Bp = Bs[c & 1];
        #pragma unroll
        for (int s = 0; s < 4; s++) {
            int kc = s * 8 + kc0;
            uint32_t af[2][4];
            #pragma unroll
            for (int mt = 0; mt < 2; mt++) {
                const float* r0p = Ap + (aR + mt * 16) * LDA;
                const float* r1p = Ap + (aR + mt * 16 + 8) * LDA;
                af[mt][0] = __float_as_uint(r0p[kc]);
                af[mt][1] = __float_as_uint(r1p[kc]);
                af[mt][2] = __float_as_uint(r0p[kc + 4]);
                af[mt][3] = __float_as_uint(r1p[kc + 4]);
            }
            #pragma unroll
            for (int nt = 0; nt < 8; nt++) {
                const float* bp = Bp + (bR + nt * 8) * LDA;
                uint32_t b0 = __float_as_uint(bp[kc]);
                uint32_t b1 = __float_as_uint(bp[kc + 4]);
                #pragma unroll
                for (int mt = 0; mt < 2; mt++)
                    mma_tf32_16n8k8(acc[mt][nt],
                                    af[mt][0], af[mt][1], af[mt][2], af[mt][3],
                                    b0, b1);
            }
        }
        if (c + 1 < nch) {
            st_chunk((c + 1) & 1);
            __syncthreads();
        }
    }

    /* epilogue */
    int rbase = m0 + wm * 32 + (lane >> 2);
    int cbase = n0 + wn * 64 + (lane & 3) * 2;
    #pragma unroll
    for (int mt = 0; mt < 2; mt++) {
        #pragma unroll
        for (int half = 0; half < 2; half++) {
            int row = rbase + mt * 16 + half * 8;
            size_t rowo = (size_t)row * N;
            #pragma unroll
            for (int nt = 0; nt < 8; nt++) {
                int col = cbase + nt * 8;
                float u0 = acc[mt][nt][half * 2 + 0] * alpha;
                float u1 = acc[mt][nt][half * 2 + 1] * alpha;
                if (EPI >= 1) {
                    u0 += __ldg(&bias[col]);
                    u1 += __ldg(&bias[col + 1]);
                }
                if (EPI == 3 || EPI == 4) {
                    u0 = gelu_exact(u0);
                    u1 = gelu_exact(u1);
                }
                if (EPI == 2 || EPI == 4) {
                    u0 += Rb[rowo + col];
                    u1 += Rb[rowo + col + 1];
                }
                float2 o2; o2.x = u0; o2.y = u1;
                *(float2*)&Cb[rowo + col] = o2;
            }
        }
    }
}

/* ------------- column (query-axis) softmax stats: partial pass ----------- */
__global__ __launch_bounds__(128) void colstat_k(
    const float* __restrict__ s, float* __restrict__ pm, float* __restrict__ ps)
{
    int j  = blockIdx.x * 128 + threadIdx.x;
    int z  = blockIdx.z;
    int i0 = blockIdx.y * ROWS_PER_CHUNK;
    const float* p = s + (size_t)z * SS * SS + (size_t)i0 * SS + j;
    float m = -1e30f, l = 0.0f;
    #pragma unroll 4
    for (int i = 0; i < ROWS_PER_CHUNK; i++) {
        float v = p[(size_t)i * SS];
        if (v <= m) {
            l += fexp(v - m);
        } else {
            l = l * fexp(m - v) + 1.0f;
            m = v;
        }
    }
    size_t o = ((size_t)blockIdx.y * BB + z) * SS + j;
    pm[o] = m;
    ps[o] = l;
}

__global__ __launch_bounds__(256) void colreduce_k(
    const float* __restrict__ pm, const float* __restrict__ ps,
    float* __restrict__ off)
{
    int idx = blockIdx.x * 256 + threadIdx.x;
    float m = -1e30f;
    #pragma unroll
    for (int c = 0; c < NCHUNK; c++) m = fmaxf(m, pm[(size_t)c * NROWS + idx]);
    float l = 0.0f;
    #pragma unroll
    for (int c = 0; c < NCHUNK; c++)
        l += ps[(size_t)c * NROWS + idx] * fexp(pm[(size_t)c * NROWS + idx] - m);
    off[idx] = m + logf(l);
}

/* ------------------------------- launch ---------------------------------- */
static float* sym(const void* s) {
    void* p = nullptr;
    cudaGetSymbolAddress(&p, s);
    return (float*)p;
}

extern "C" void kernel_launch(void* const* d_in, const int* in_sizes, int n_in,
                              void* d_out, int out_size)
{
    const float* x    = (const float*)d_in[0];
    const float* ln1w = (const float*)d_in[1];
    const float* ln1b = (const float*)d_in[2];
    const float* wq   = (const float*)d_in[3];
    const float* bq   = (const float*)d_in[4];
    const float* wk   = (const float*)d_in[5];
    const float* bk   = (const float*)d_in[6];
    const float* wv   = (const float*)d_in[7];
    const float* bv   = (const float*)d_in[8];
    const float* wo   = (const float*)d_in[9];
    const float* bo   = (const float*)d_in[10];
    const float* ln2w = (const float*)d_in[11];
    const float* ln2b = (const float*)d_in[12];
    const float* w1   = (const float*)d_in[13];
    const float* b1   = (const float*)d_in[14];
    const float* w2   = (const float*)d_in[15];
    const float* b2   = (const float*)d_in[16];
    float* out = (float*)d_out;

    float* pt   = sym(g_t);
    float* pxl  = sym(g_xl);
    float* pq   = sym(g_q);
    float* pk   = sym(g_k);
    float* pv   = sym(g_v);
    float* pvT  = sym(g_vT);
    float* py   = sym(g_y);
    float* pao  = sym(g_ao);
    float* pfin = sym(g_fin);
    float* ph_  = sym(g_h);
    float* psc  = sym(g_scores);
    float* ppm  = sym(g_pm);
    float* pps  = sym(g_ps);
    float* poff = sym(g_off);
    float* pwqT = sym(g_wqT);
    float* pwkT = sym(g_wkT);
    float* pwvT = sym(g_wvT);
    float* pwoT = sym(g_woT);
    float* pw1T = sym(g_w1T);
    float* pw2T = sym(g_w2T);

    cudaFuncSetAttribute(gemm_mma<0,0>, cudaFuncAttributeMaxDynamicSharedMemorySize, GEMM_SMEM);
    cudaFuncSetAttribute(gemm_mma<0,1>, cudaFuncAttributeMaxDynamicSharedMemorySize, GEMM_SMEM);
    cudaFuncSetAttribute(gemm_mma<0,2>, cudaFuncAttributeMaxDynamicSharedMemorySize, GEMM_SMEM);
    cudaFuncSetAttribute(gemm_mma<0,3>, cudaFuncAttributeMaxDynamicSharedMemorySize, GEMM_SMEM);
    cudaFuncSetAttribute(gemm_mma<0,4>, cudaFuncAttributeMaxDynamicSharedMemorySize, GEMM_SMEM);
    cudaFuncSetAttribute(gemm_mma<1,0>, cudaFuncAttributeMaxDynamicSharedMemorySize, GEMM_SMEM);

    dim3 tb(32, 32);
    const long long sSC = (long long)SS * CCH;
    const long long sS2 = (long long)SS * SS;

    /* x [B,C,S] -> t [B,S,C] */
    transpose_k<<<dim3(SS/32, CCH/32, BB), tb>>>(x, pt, CCH, SS);

    /* LN1 */
    ln_k<<<NROWS/8, 256>>>(pt, ln1w, ln1b, pxl);

    /* weight transposes (W[K,N] -> W^T[N,K]) */
    transpose_k<<<dim3(4, 4, 1), tb>>>(wq, pwqT, CCH, CCH);
    transpose_k<<<dim3(4, 4, 1), tb>>>(wk, pwkT, CCH, CCH);
    transpose_k<<<dim3(4, 4, 1), tb>>>(wv, pwvT, CCH, CCH);
    transpose_k<<<dim3(4, 4, 1), tb>>>(wo, pwoT, CCH, CCH);
    transpose_k<<<dim3(8, 4, 1), tb>>>(w1, pw1T, CCH, HIDN);
    transpose_k<<<dim3(4, 8, 1), tb>>>(w2, pw2T, HIDN, CCH);

    /* QKV projections */
    gemm_mma<0,1><<<dim3(1, NROWS/128, 1), 256, GEMM_SMEM>>>(pxl, pwqT, bq, nullptr, pq,
        CCH, CCH, 0, 0, 0, nullptr, 0, 1.0f);
    gemm_mma<0,1><<<dim3(1, NROWS/128, 1), 256, GEMM_SMEM>>>(pxl, pwkT, bk, nullptr, pk,
        CCH, CCH, 0, 0, 0, nullptr, 0, 1.0f);
    gemm_mma<0,1><<<dim3(1, NROWS/128, 1), 256, GEMM_SMEM>>>(pxl, pwvT, bv, nullptr, pv,
        CCH, CCH, 0, 0, 0, nullptr, 0, 1.0f);

    /* scores = 0.25 * q @ k^T (batched, K-major both) */
    gemm_mma<0,0><<<dim3(SS/128, SS/128, BB), 256, GEMM_SMEM>>>(pq, pk, nullptr, nullptr, psc,
        SS, CCH, sSC, sSC, sS2, nullptr, 0, 0.25f);

    /* column softmax stats */
    colstat_k<<<dim3(SS/128, NCHUNK, BB), 128>>>(psc, ppm, pps);
    colreduce_k<<<NROWS/256, 256>>>(ppm, pps, poff);

    /* v -> vT per batch */
    transpose_k<<<dim3(CCH/32, SS/32, BB), tb>>>(pv, pvT, SS, CCH);

    /* ao = exp(scores - off) @ v (A-mode exp on tile load) */
    gemm_mma<1,0><<<dim3(1, SS/128, BB), 256, GEMM_SMEM>>>(psc, pvT, nullptr, nullptr, pao,
        CCH, SS, sS2, sSC, sSC, poff, SS, 1.0f);

    /* y = ao @ wo + bo + t */
    gemm_mma<0,2><<<dim3(1, NROWS/128, 1), 256, GEMM_SMEM>>>(pao, pwoT, bo, pt, py,
        CCH, CCH, 0, 0, 0, nullptr, 0, 1.0f);

    /* LN2 */
    ln_k<<<NROWS/8, 256>>>(py, ln2w, ln2b, pxl);

    /* h = gelu(ln2 @ w1 + b1) */
    gemm_mma<0,3><<<dim3(HIDN/128, NROWS/128, 1), 256, GEMM_SMEM>>>(pxl, pw1T, b1, nullptr, ph_,
        HIDN, CCH, 0, 0, 0, nullptr, 0, 1.0f);

    /* fin = gelu(h @ w2 + b2) + y */
    gemm_mma<0,4><<<dim3(1, NROWS/128, 1), 256, GEMM_SMEM>>>(ph_, pw2T, b2, py, pfin,
        CCH, HIDN, 0, 0, 0, nullptr, 0, 1.0f);

    /* fin [B,S,C] -> out [B,C,H,W] */
    transpose_k<<<dim3(CCH/32, SS/32, BB), tb>>>(pfin, out, SS, CCH);
}